// round 15
// baseline (speedup 1.0000x reference)
#include <cuda_runtime.h>
#include <cuda_bf16.h>
#include <math.h>

typedef unsigned int u32;
typedef unsigned long long u64;

#define B_  64
#define T_  512
#define D_  512
#define H_  1024
#define G4  4096
#define M1  32768          // B_*T_
#define NBLK 128
#define RTH 512

// ---- lstm_persist smem layout (bytes) ----
#define A_STRIDE_B 2064                 // 1032 bf16/row (odd multiple of 16B)
#define SM_AHI 0
#define SM_ALO (32 * A_STRIDE_B)        // 66048
#define SM_B   (2 * 32 * A_STRIDE_B)    // 132096
#define B_STRIDE_B 272                  // 136 bf16/row (odd multiple of 16B)
#define B_LO_OFF 17408                  // 64 * 272
#define BST 34816                       // per chunk buffer (hi + lo)
#define SM_DX (SM_B + 2 * BST)          // 201728
#define DX_S 66
#define SMEM_TOTAL (SM_DX + 2 * 32 * DX_S * 4)   // 218624

// ---- gemm_xw_mma smem layout ----
#define P1_STRIDE 144                   // 64 bf16 = 128B + 16B pad
#define P1_AHI 0
#define P1_ALO 18432
#define P1_BHI 36864
#define P1_BLO 55296
#define P1_STAGE 73728
#define P1_SMEM (2 * P1_STAGE)          // 147456

// ---------------------------------------------------------------------------
// Device globals (allocation-free scratch)
// ---------------------------------------------------------------------------
__device__ float g_xg[(size_t)M1 * G4];              // xg = x@Wx + b (512 MB)
__device__ __nv_bfloat16 g_xhi[(size_t)M1 * D_];
__device__ __nv_bfloat16 g_xlo[(size_t)M1 * D_];
__device__ __nv_bfloat16 g_wxthi[(size_t)G4 * D_];   // Wx^T hi [n][k]
__device__ __nv_bfloat16 g_wxtlo[(size_t)G4 * D_];
__device__ __nv_bfloat16 g_wthi[(size_t)G4 * H_];    // Wh^T hi [m_global][k]
__device__ __nv_bfloat16 g_wtlo[(size_t)G4 * H_];
__device__ __nv_bfloat16 g_hh[2][B_ * H_];           // h hi [b][k] double-buffered
__device__ __nv_bfloat16 g_hl[2][B_ * H_];           // h lo
__device__ __align__(16) unsigned g_flags[NBLK];     // per-block barrier generations

// ---------------------------------------------------------------------------
// helpers
// ---------------------------------------------------------------------------
__device__ __forceinline__ u32 smem_u32(const void* p) {
    u32 a;
    asm("{ .reg .u64 t; cvta.to.shared.u64 t, %1; cvt.u32.u64 %0, t; }"
        : "=r"(a) : "l"(p));
    return a;
}
__device__ __forceinline__ void ldsm4(u32* r, u32 addr) {
    asm volatile("ldmatrix.sync.aligned.m8n8.x4.shared.b16 {%0,%1,%2,%3}, [%4];"
                 : "=r"(r[0]), "=r"(r[1]), "=r"(r[2]), "=r"(r[3]) : "r"(addr));
}
__device__ __forceinline__ void mma_bf16(float* d, const u32* a, u32 b0, u32 b1) {
    asm volatile(
        "mma.sync.aligned.m16n8k16.row.col.f32.bf16.bf16.f32 "
        "{%0,%1,%2,%3}, {%4,%5,%6,%7}, {%8,%9}, {%0,%1,%2,%3};"
        : "+f"(d[0]), "+f"(d[1]), "+f"(d[2]), "+f"(d[3])
        : "r"(a[0]), "r"(a[1]), "r"(a[2]), "r"(a[3]), "r"(b0), "r"(b1));
}
__device__ __forceinline__ void cpasync16(u32 dst, const void* src) {
    asm volatile("cp.async.cg.shared.global [%0], [%1], 16;" :: "r"(dst), "l"(src));
}

// ---------------------------------------------------------------------------
// init: zero h buffers and barrier flags (runs every launch/replay)
// ---------------------------------------------------------------------------
__global__ void init_state() {
    int idx = blockIdx.x * blockDim.x + threadIdx.x;   // 65536
    g_hh[0][idx] = __float2bfloat16(0.0f);
    g_hl[0][idx] = __float2bfloat16(0.0f);
    if (idx < NBLK) g_flags[idx] = 0u;
}

// ---------------------------------------------------------------------------
// prep kernels
// ---------------------------------------------------------------------------
__global__ void prep_x(const float* __restrict__ x) {
    size_t i = (size_t)blockIdx.x * 1024 + threadIdx.x;
    float v = x[i];
    __nv_bfloat16 hi = __float2bfloat16(v);
    g_xhi[i] = hi;
    g_xlo[i] = __float2bfloat16(v - __bfloat162float(hi));
}

__global__ void prep_wxT(const float* __restrict__ Wx) {
    __shared__ float ts[32][33];
    const int k0 = blockIdx.x * 32;
    const int c0 = blockIdx.y * 32;
    const int txl = threadIdx.x, tyl = threadIdx.y;
#pragma unroll
    for (int r = 0; r < 4; ++r) {
        int kr = tyl + 8 * r;
        ts[kr][txl] = Wx[(size_t)(k0 + kr) * G4 + c0 + txl];
    }
    __syncthreads();
#pragma unroll
    for (int r = 0; r < 4; ++r) {
        int cl = tyl + 8 * r;
        int c = c0 + cl;
        float w = ts[txl][cl];
        __nv_bfloat16 hi = __float2bfloat16(w);
        g_wxthi[(size_t)c * D_ + k0 + txl] = hi;
        g_wxtlo[(size_t)c * D_ + k0 + txl] =
            __float2bfloat16(w - __bfloat162float(hi));
    }
}

__global__ void prep_whT(const float* __restrict__ Wh) {
    __shared__ float ts[32][33];
    const int k0 = blockIdx.x * 32;
    const int c0 = blockIdx.y * 32;
    const int txl = threadIdx.x, tyl = threadIdx.y;
#pragma unroll
    for (int r = 0; r < 4; ++r) {
        int kr = tyl + 8 * r;
        ts[kr][txl] = Wh[(size_t)(k0 + kr) * G4 + c0 + txl];
    }
    __syncthreads();
#pragma unroll
    for (int r = 0; r < 4; ++r) {
        int cl = tyl + 8 * r;
        int c = c0 + cl;
        int bx = (c & 1023) >> 3;
        int g  = c >> 10;
        int jj = c & 7;
        int mg = bx * 32 + jj * 4 + g;
        float w = ts[txl][cl];
        __nv_bfloat16 hi = __float2bfloat16(w);
        g_wthi[(size_t)mg * H_ + k0 + txl] = hi;
        g_wtlo[(size_t)mg * H_ + k0 + txl] =
            __float2bfloat16(w - __bfloat162float(hi));
    }
}

// ---------------------------------------------------------------------------
// Phase 1 via mma.sync (known-good from R13)
// ---------------------------------------------------------------------------
__global__ void __launch_bounds__(256, 1)
gemm_xw_mma(const float* __restrict__ bias) {
    extern __shared__ char smc[];
    const u32 sb = smem_u32(smc);
    const int tid = threadIdx.x;
    const int wid = tid >> 5;
    const int lane = tid & 31;
    const int bm = blockIdx.y, bn = blockIdx.x;

    const int wm = (wid >> 1) * 32;
    const int wn = (wid & 1) * 64;

    float acc[2][8][4];
#pragma unroll
    for (int m = 0; m < 2; ++m)
#pragma unroll
        for (int f = 0; f < 8; ++f)
#pragma unroll
            for (int v = 0; v < 4; ++v) acc[m][f][v] = 0.0f;

    const u32 aLane = (u32)((lane & 15) * P1_STRIDE + ((lane >> 4) << 4));
    const u32 bLane = (u32)(((((lane >> 4) << 3) + (lane & 7)) * P1_STRIDE) +
                            (((lane >> 3) & 1) << 4));

    auto issue = [&](int kc, int s) {
        const u32 st = sb + (u32)s * P1_STAGE;
#pragma unroll
        for (int it = 0; it < 4; ++it) {
            int cid = tid + it * 256;
            int r = cid >> 3, c = cid & 7;
            u32 doff = (u32)(r * P1_STRIDE + c * 16);
            size_t sia = (((size_t)(bm * 128 + r)) << 9) + kc * 64 + c * 8;
            size_t sib = (((size_t)(bn * 128 + r)) << 9) + kc * 64 + c * 8;
            cpasync16(st + P1_AHI + doff, g_xhi + sia);
            cpasync16(st + P1_ALO + doff, g_xlo + sia);
            cpasync16(st + P1_BHI + doff, g_wxthi + sib);
            cpasync16(st + P1_BLO + doff, g_wxtlo + sib);
        }
        asm volatile("cp.async.commit_group;");
    };

    issue(0, 0);
#pragma unroll 1
    for (int kc = 0; kc < 8; ++kc) {
        if (kc < 7) {
            issue(kc + 1, (kc + 1) & 1);
            asm volatile("cp.async.wait_group 1;");
        } else {
            asm volatile("cp.async.wait_group 0;");
        }
        __syncthreads();
        const u32 st = sb + (u32)(kc & 1) * P1_STAGE;
        const u32 aB = st + P1_AHI + (u32)(wm * P1_STRIDE) + aLane;
        const u32 bB = st + P1_BHI + (u32)(wn * P1_STRIDE) + bLane;
#pragma unroll
        for (int kt = 0; kt < 4; ++kt) {
            const u32 ka = (u32)(kt * 32);
            u32 ah0[4], ah1[4], al0[4], al1[4];
            ldsm4(ah0, aB + ka);
            ldsm4(ah1, aB + 16 * P1_STRIDE + ka);
            ldsm4(al0, aB + (P1_ALO - P1_AHI) + ka);
            ldsm4(al1, aB + (P1_ALO - P1_AHI) + 16 * P1_STRIDE + ka);
#pragma unroll
            for (int s = 0; s < 4; ++s) {
                u32 bh[4], bl[4];
                ldsm4(bh, bB + (u32)(s * 16 * P1_STRIDE) + ka);
                ldsm4(bl, bB + (u32)(s * 16 * P1_STRIDE) + (P1_BLO - P1_BHI) + ka);
                mma_bf16(acc[0][2*s],   ah0, bh[0], bh[1]);
                mma_bf16(acc[0][2*s+1], ah0, bh[2], bh[3]);
                mma_bf16(acc[1][2*s],   ah1, bh[0], bh[1]);
                mma_bf16(acc[1][2*s+1], ah1, bh[2], bh[3]);
                mma_bf16(acc[0][2*s],   al0, bh[0], bh[1]);
                mma_bf16(acc[0][2*s+1], al0, bh[2], bh[3]);
                mma_bf16(acc[1][2*s],   al1, bh[0], bh[1]);
                mma_bf16(acc[1][2*s+1], al1, bh[2], bh[3]);
                mma_bf16(acc[0][2*s],   ah0, bl[0], bl[1]);
                mma_bf16(acc[0][2*s+1], ah0, bl[2], bl[3]);
                mma_bf16(acc[1][2*s],   ah1, bl[0], bl[1]);
                mma_bf16(acc[1][2*s+1], ah1, bl[2], bl[3]);
            }
        }
        __syncthreads();
    }

#pragma unroll
    for (int m = 0; m < 2; ++m) {
        int r0 = bm * 128 + wm + m * 16 + (lane >> 2);
#pragma unroll
        for (int f = 0; f < 8; ++f) {
            int col = bn * 128 + wn + f * 8 + 2 * (lane & 3);
            float b0 = bias[col], b1 = bias[col + 1];
            float* p0 = g_xg + (size_t)r0 * G4 + col;
            float* p1 = p0 + (size_t)8 * G4;
            *(float2*)p0 = make_float2(acc[m][f][0] + b0, acc[m][f][1] + b1);
            *(float2*)p1 = make_float2(acc[m][f][2] + b0, acc[m][f][3] + b1);
        }
    }
}

// ---------------------------------------------------------------------------
// Contention-free grid barrier: per-block release flag + v4 acquire polling.
// All NBLK blocks resident by construction (1 block/SM).
// ---------------------------------------------------------------------------
__device__ __forceinline__ void grid_barrier(unsigned target) {
    __threadfence();
    __syncthreads();
    if (threadIdx.x == 0) {
        asm volatile("st.global.release.gpu.u32 [%0], %1;"
                     :: "l"(g_flags + blockIdx.x), "r"(target) : "memory");
    }
    if (threadIdx.x < 32) {
        const uint4* p = (const uint4*)g_flags + threadIdx.x;  // 32 lanes x 4 flags
        u32 a, b, c, d;
        do {
            asm volatile("ld.global.acquire.gpu.v4.u32 {%0,%1,%2,%3}, [%4];"
                         : "=r"(a), "=r"(b), "=r"(c), "=r"(d) : "l"(p));
        } while (a < target || b < target || c < target || d < target);
    }
    __syncthreads();
}

// ---------------------------------------------------------------------------
// Persistent mma.sync recurrence (R13 structure). Block bx: M=32 gate-cols
// (m=jj*4+g), N=64 batch, K=1024. 16 warps = 8 tiles (16m x 16n) x 2
// K-sections; chunk pairs staged together. WhT hi/lo resident in smem.
// D = A_hi@h_hi + A_lo@h_hi + A_hi@h_lo, fp32 register accumulators.
// ---------------------------------------------------------------------------
__global__ void __launch_bounds__(RTH, 1)
lstm_persist(float* __restrict__ out) {
    extern __shared__ char smc[];
    const u32 sb = smem_u32(smc);
    const int tid = threadIdx.x;
    const int wid = tid >> 5;
    const int lane = tid & 31;
    const int bx = blockIdx.x;
    const int m0g = bx * 32;
    const int j0 = bx * 8;

    // one-time resident A: WhT hi/lo [32][1024] bf16
#pragma unroll
    for (int it = 0; it < 8; ++it) {
        int cid = tid + it * RTH;            // 0..4095
        int row = cid >> 7, c = cid & 127;
        size_t si = ((size_t)(m0g + row) << 10) + c * 8;
        *(uint4*)(smc + SM_AHI + row * A_STRIDE_B + c * 16) =
            __ldg((const uint4*)(g_wthi + si));
        *(uint4*)(smc + SM_ALO + row * A_STRIDE_B + c * 16) =
            __ldg((const uint4*)(g_wtlo + si));
    }

    const int tile = wid & 7;
    const int ksec = wid >> 3;               // 0 -> even chunks, 1 -> odd
    const int wm = (tile >> 2) * 16;
    const int wn = (tile & 3) * 16;

    const u32 aAddrHi = sb + SM_AHI + (u32)((wm + (lane & 15)) * A_STRIDE_B +
                                            ((lane >> 4) << 4));
    const u32 aAddrLo = aAddrHi + (u32)(SM_ALO - SM_AHI);
    const int bn_row = wn + ((lane >> 4) << 3) + (lane & 7);
    const u32 bbase = sb + SM_B + (u32)ksec * BST +
                      (u32)(bn_row * B_STRIDE_B + (((lane >> 3) & 1) << 4));

    // pointwise: one cell per thread
    const int pb = tid >> 3;                 // batch 0..63
    const int pj = tid & 7;                  // hidden col within block
    float cc = 0.0f;

    __syncthreads();

    for (int t = 0; t < T_; ++t) {
        const __nv_bfloat16* hhi = g_hh[t & 1];
        const __nv_bfloat16* hlo = g_hl[t & 1];
        __nv_bfloat16* hh_nxt = g_hh[(t + 1) & 1];
        __nv_bfloat16* hl_nxt = g_hl[(t + 1) & 1];

        float xv[4];
        {
            const float* xgb = g_xg + ((size_t)pb * T_ + t) * G4 + j0 + pj;
#pragma unroll
            for (int g = 0; g < 4; ++g) xv[g] = __ldcs(xgb + g * H_);
        }

        float acc0[4] = {0.f, 0.f, 0.f, 0.f};
        float acc1[4] = {0.f, 0.f, 0.f, 0.f};

        // stage pair 0 (chunks 0 -> buf0, 1 -> buf1)
#pragma unroll
        for (int q = 0; q < 2; ++q)
#pragma unroll
            for (int it = 0; it < 2; ++it) {
                int cid = tid + it * RTH;
                int row = cid >> 4, c = cid & 15;
                size_t si = ((size_t)row << 10) + q * 128 + c * 8;
                uint4 vh = __ldcg((const uint4*)(hhi + si));
                uint4 vl = __ldcg((const uint4*)(hlo + si));
                char* d = smc + SM_B + q * BST + row * B_STRIDE_B + c * 16;
                *(uint4*)d = vh;
                *(uint4*)(d + B_LO_OFF) = vl;
            }
        __syncthreads();

#pragma unroll 1
        for (int p = 0; p < 4; ++p) {
            uint4 rh[2][2], rl[2][2];
            if (p < 3) {
#pragma unroll
                for (int q = 0; q < 2; ++q)
#pragma unroll
                    for (int it = 0; it < 2; ++it) {
                        int cid = tid + it * RTH;
                        int row = cid >> 4, c = cid & 15;
                        size_t si = ((size_t)row << 10) + (p + 1) * 256 + q * 128 + c * 8;
                        rh[q][it] = __ldcg((const uint4*)(hhi + si));
                        rl[q][it] = __ldcg((const uint4*)(hlo + si));
                    }
            }
            // compute own chunk: kc = 2p + ksec, from buffer `ksec`
            const u32 abase = (u32)((2 * p + ksec) * 256);
#pragma unroll
            for (int kt = 0; kt < 8; ++kt) {
                u32 ahi[4], alo[4], bhi[4], blo[4];
                ldsm4(ahi, aAddrHi + abase + kt * 32);
                ldsm4(alo, aAddrLo + abase + kt * 32);
                ldsm4(bhi, bbase + kt * 32);
                ldsm4(blo, bbase + B_LO_OFF + kt * 32);
                mma_bf16(acc0, ahi, bhi[0], bhi[1]);
                mma_bf16(acc1, ahi, bhi[2], bhi[3]);
                mma_bf16(acc0, alo, bhi[0], bhi[1]);
                mma_bf16(acc1, alo, bhi[2], bhi[3]);
                mma_bf16(acc0, ahi, blo[0], blo[1]);
                mma_bf16(acc1, ahi, blo[2], blo[3]);
            }
            __syncthreads();
            if (p < 3) {
#pragma unroll
                for (int q = 0; q < 2; ++q)
#pragma unroll
                    for (int it = 0; it < 2; ++it) {
                        int cid = tid + it * RTH;
                        int row = cid >> 4, c = cid & 15;
                        char* d = smc + SM_B + q * BST + row * B_STRIDE_B + c * 16;
                        *(uint4*)d = rh[q][it];
                        *(uint4*)(d + B_LO_OFF) = rl[q][it];
                    }
                __syncthreads();
            }
        }

        // write D fragments: Dx[ksec][32][66]
        {
            float* dx = (float*)(smc + SM_DX) + ksec * (32 * DX_S);
            int r0 = wm + (lane >> 2);
            int col = wn + 2 * (lane & 3);
            dx[r0 * DX_S + col]           = acc0[0];
            dx[r0 * DX_S + col + 1]       = acc0[1];
            dx[(r0 + 8) * DX_S + col]     = acc0[2];
            dx[(r0 + 8) * DX_S + col + 1] = acc0[3];
            dx[r0 * DX_S + col + 8]       = acc1[0];
            dx[r0 * DX_S + col + 9]       = acc1[1];
            dx[(r0 + 8) * DX_S + col + 8] = acc1[2];
            dx[(r0 + 8) * DX_S + col + 9] = acc1[3];
        }
        __syncthreads();

        // pointwise: one cell per thread
        {
            const float* dx0 = (const float*)(smc + SM_DX);
            const float* dx1 = dx0 + 32 * DX_S;
            int m = pj << 2;
            float vi = dx0[(m + 0) * DX_S + pb] + dx1[(m + 0) * DX_S + pb] + xv[0];
            float vf = dx0[(m + 1) * DX_S + pb] + dx1[(m + 1) * DX_S + pb] + xv[1];
            float vg = dx0[(m + 2) * DX_S + pb] + dx1[(m + 2) * DX_S + pb] + xv[2];
            float vo = dx0[(m + 3) * DX_S + pb] + dx1[(m + 3) * DX_S + pb] + xv[3];
            float si = 1.0f / (1.0f + expf(-vi));
            float sf = 1.0f / (1.0f + expf(-vf));
            float tg = tanhf(vg);
            float so = 1.0f / (1.0f + expf(-vo));
            float c = sf * cc + si * tg;
            cc = c;
            float h = so * tanhf(c);
            __nv_bfloat16 hb = __float2bfloat16(h);
            hh_nxt[(pb << 10) + j0 + pj] = hb;
            hl_nxt[(pb << 10) + j0 + pj] =
                __float2bfloat16(h - __bfloat162float(hb));
            out[((size_t)pb * T_ + t) * H_ + j0 + pj] = h;
        }

        if (t < T_ - 1) grid_barrier((unsigned)(t + 1));
    }
}

// ---------------------------------------------------------------------------
// Launch: 6 graph nodes (lstm_persist last)
// ---------------------------------------------------------------------------
extern "C" void kernel_launch(void* const* d_in, const int* in_sizes, int n_in,
                              void* d_out, int out_size) {
    const float* x    = (const float*)d_in[0];   // [B, T, D]
    const float* Wx   = (const float*)d_in[1];   // [D, 4H]
    const float* Wh   = (const float*)d_in[2];   // [H, 4H]
    const float* bias = (const float*)d_in[3];   // [4H]
    float* out = (float*)d_out;                  // [B, T, H]

    cudaFuncSetAttribute(lstm_persist,
                         cudaFuncAttributeMaxDynamicSharedMemorySize, SMEM_TOTAL);
    cudaFuncSetAttribute(gemm_xw_mma,
                         cudaFuncAttributeMaxDynamicSharedMemorySize, P1_SMEM);

    init_state<<<256, 256>>>();
    prep_x<<<M1 * D_ / 1024, 1024>>>(x);
    prep_wxT<<<dim3(D_ / 32, G4 / 32), dim3(32, 8)>>>(Wx);
    prep_whT<<<dim3(H_ / 32, G4 / 32), dim3(32, 8)>>>(Wh);
    gemm_xw_mma<<<dim3(G4 / 128, M1 / 128), 256, P1_SMEM>>>(bias);
    lstm_persist<<<NBLK, RTH, SMEM_TOTAL>>>(out);
}

// round 16
// speedup vs baseline: 1.9691x; 1.9691x over previous
#include <cuda_runtime.h>
#include <cuda_fp16.h>
#include <math.h>

typedef unsigned int u32;
typedef unsigned long long u64;

#define B_  64
#define T_  512
#define D_  512
#define H_  1024
#define G4  4096
#define M1  32768          // B_*T_
#define NBLK 128
#define RTH 512

// ---- lstm_persist smem layout (bytes) ----
#define A_STRIDE_B 2064                 // 1024 fp16 = 2048B + 16B pad
#define SM_AHI 0
#define SM_ALO (32 * A_STRIDE_B)        // 66048
#define SM_B   (2 * 32 * A_STRIDE_B)    // 132096
#define B_STRIDE_B 272                  // 128 fp16 = 256B + 16B pad
#define BST (64 * B_STRIDE_B)           // 17408 per chunk buffer
#define SM_DX (SM_B + 2 * BST)          // 166912
#define DX_S 66
#define SMEM_TOTAL (SM_DX + 2 * 32 * DX_S * 4)   // 183808

// ---- gemm_xw_mma smem layout ----
#define P1_STRIDE 144                   // 64 fp16 = 128B + 16B pad
#define P1_A   0
#define P1_BHI 18432
#define P1_BLO 36864
#define P1_STAGE 55296
#define P1_SMEM (2 * P1_STAGE)          // 110592

// ---------------------------------------------------------------------------
// Device globals (allocation-free scratch)
// ---------------------------------------------------------------------------
__device__ float g_xg[(size_t)M1 * G4];              // xg = x@Wx + b (512 MB)
__device__ __half g_xh[(size_t)M1 * D_];             // x fp16 (32 MB)
__device__ __half g_wxthi[(size_t)G4 * D_];          // Wx^T hi [n][k]
__device__ __half g_wxtlo[(size_t)G4 * D_];          // Wx^T lo
__device__ __half g_wthi[(size_t)G4 * H_];           // Wh^T hi [m_global][k]
__device__ __half g_wtlo[(size_t)G4 * H_];           // Wh^T lo
__device__ __half g_hf[2][B_ * H_];                  // h fp16 [b][k] double-buffered
__device__ unsigned g_cnt;
__device__ unsigned g_gen;

// ---------------------------------------------------------------------------
// helpers
// ---------------------------------------------------------------------------
__device__ __forceinline__ u32 smem_u32(const void* p) {
    u32 a;
    asm("{ .reg .u64 t; cvta.to.shared.u64 t, %1; cvt.u32.u64 %0, t; }"
        : "=r"(a) : "l"(p));
    return a;
}
__device__ __forceinline__ void ldsm4(u32* r, u32 addr) {
    asm volatile("ldmatrix.sync.aligned.m8n8.x4.shared.b16 {%0,%1,%2,%3}, [%4];"
                 : "=r"(r[0]), "=r"(r[1]), "=r"(r[2]), "=r"(r[3]) : "r"(addr));
}
__device__ __forceinline__ void mma_f16(float* d, const u32* a, u32 b0, u32 b1) {
    asm volatile(
        "mma.sync.aligned.m16n8k16.row.col.f32.f16.f16.f32 "
        "{%0,%1,%2,%3}, {%4,%5,%6,%7}, {%8,%9}, {%0,%1,%2,%3};"
        : "+f"(d[0]), "+f"(d[1]), "+f"(d[2]), "+f"(d[3])
        : "r"(a[0]), "r"(a[1]), "r"(a[2]), "r"(a[3]), "r"(b0), "r"(b1));
}
__device__ __forceinline__ void cpasync16(u32 dst, const void* src) {
    asm volatile("cp.async.cg.shared.global [%0], [%1], 16;" :: "r"(dst), "l"(src));
}

// ---------------------------------------------------------------------------
// init: zero h buffer 0 and barrier counter (runs every launch/replay)
// ---------------------------------------------------------------------------
__global__ void init_state() {
    int idx = blockIdx.x * blockDim.x + threadIdx.x;   // 65536
    g_hf[0][idx] = __float2half(0.0f);
    if (idx == 0) g_cnt = 0u;
}

// ---------------------------------------------------------------------------
// prep kernels
// ---------------------------------------------------------------------------
__global__ void prep_x(const float* __restrict__ x) {
    size_t i = (size_t)blockIdx.x * 1024 + threadIdx.x;
    g_xh[i] = __float2half_rn(x[i]);
}

__global__ void prep_wxT(const float* __restrict__ Wx) {
    __shared__ float ts[32][33];
    const int k0 = blockIdx.x * 32;
    const int c0 = blockIdx.y * 32;
    const int txl = threadIdx.x, tyl = threadIdx.y;   // (32, 8)
#pragma unroll
    for (int r = 0; r < 4; ++r) {
        int kr = tyl + 8 * r;
        ts[kr][txl] = Wx[(size_t)(k0 + kr) * G4 + c0 + txl];
    }
    __syncthreads();
#pragma unroll
    for (int r = 0; r < 4; ++r) {
        int cl = tyl + 8 * r;
        int c = c0 + cl;
        float w = ts[txl][cl];
        __half hi = __float2half_rn(w);
        g_wxthi[(size_t)c * D_ + k0 + txl] = hi;
        g_wxtlo[(size_t)c * D_ + k0 + txl] =
            __float2half_rn(w - __half2float(hi));
    }
}

__global__ void prep_whT(const float* __restrict__ Wh) {
    __shared__ float ts[32][33];
    const int k0 = blockIdx.x * 32;
    const int c0 = blockIdx.y * 32;
    const int txl = threadIdx.x, tyl = threadIdx.y;
#pragma unroll
    for (int r = 0; r < 4; ++r) {
        int kr = tyl + 8 * r;
        ts[kr][txl] = Wh[(size_t)(k0 + kr) * G4 + c0 + txl];
    }
    __syncthreads();
#pragma unroll
    for (int r = 0; r < 4; ++r) {
        int cl = tyl + 8 * r;
        int c = c0 + cl;
        int bx = (c & 1023) >> 3;
        int g  = c >> 10;
        int jj = c & 7;
        int mg = bx * 32 + jj * 4 + g;
        float w = ts[txl][cl];
        __half hi = __float2half_rn(w);
        g_wthi[(size_t)mg * H_ + k0 + txl] = hi;
        g_wtlo[(size_t)mg * H_ + k0 + txl] =
            __float2half_rn(w - __half2float(hi));
    }
}

// ---------------------------------------------------------------------------
// Phase 1 via mma.sync: xg = x@Wx + bias. fp16 2-pass (x single, WxT hi/lo).
// Block 128m x 128n, BK=64, cp.async double-buffered. 8 warps: 32m x 64n.
// ---------------------------------------------------------------------------
__global__ void __launch_bounds__(256, 1)
gemm_xw_mma(const float* __restrict__ bias) {
    extern __shared__ char smc[];
    const u32 sb = smem_u32(smc);
    const int tid = threadIdx.x;
    const int wid = tid >> 5;
    const int lane = tid & 31;
    const int bm = blockIdx.y, bn = blockIdx.x;

    const int wm = (wid >> 1) * 32;
    const int wn = (wid & 1) * 64;

    float acc[2][8][4];
#pragma unroll
    for (int m = 0; m < 2; ++m)
#pragma unroll
        for (int f = 0; f < 8; ++f)
#pragma unroll
            for (int v = 0; v < 4; ++v) acc[m][f][v] = 0.0f;

    const u32 aLane = (u32)((lane & 15) * P1_STRIDE + ((lane >> 4) << 4));
    const u32 bLane = (u32)(((((lane >> 4) << 3) + (lane & 7)) * P1_STRIDE) +
                            (((lane >> 3) & 1) << 4));

    auto issue = [&](int kc, int s) {
        const u32 st = sb + (u32)s * P1_STAGE;
        // A: 128 rows x 64 fp16 = 1024 x 16B
#pragma unroll
        for (int it = 0; it < 4; ++it) {
            int cid = tid + it * 256;
            int r = cid >> 3, c = cid & 7;
            u32 doff = (u32)(r * P1_STRIDE + c * 16);
            size_t sia = (((size_t)(bm * 128 + r)) << 9) + kc * 64 + c * 8;
            size_t sib = (((size_t)(bn * 128 + r)) << 9) + kc * 64 + c * 8;
            cpasync16(st + P1_A + doff, g_xh + sia);
            cpasync16(st + P1_BHI + doff, g_wxthi + sib);
            cpasync16(st + P1_BLO + doff, g_wxtlo + sib);
        }
        asm volatile("cp.async.commit_group;");
    };

    issue(0, 0);
#pragma unroll 1
    for (int kc = 0; kc < 8; ++kc) {
        if (kc < 7) {
            issue(kc + 1, (kc + 1) & 1);
            asm volatile("cp.async.wait_group 1;");
        } else {
            asm volatile("cp.async.wait_group 0;");
        }
        __syncthreads();
        const u32 st = sb + (u32)(kc & 1) * P1_STAGE;
        const u32 aB = st + P1_A + (u32)(wm * P1_STRIDE) + aLane;
        const u32 bB = st + P1_BHI + (u32)(wn * P1_STRIDE) + bLane;
#pragma unroll
        for (int kt = 0; kt < 4; ++kt) {
            const u32 ka = (u32)(kt * 32);
            u32 a0[4], a1[4];
            ldsm4(a0, aB + ka);
            ldsm4(a1, aB + 16 * P1_STRIDE + ka);
#pragma unroll
            for (int s = 0; s < 4; ++s) {
                u32 bh[4], bl[4];
                ldsm4(bh, bB + (u32)(s * 16 * P1_STRIDE) + ka);
                ldsm4(bl, bB + (u32)(s * 16 * P1_STRIDE) + (P1_BLO - P1_BHI) + ka);
                mma_f16(acc[0][2*s],   a0, bh[0], bh[1]);
                mma_f16(acc[0][2*s+1], a0, bh[2], bh[3]);
                mma_f16(acc[1][2*s],   a1, bh[0], bh[1]);
                mma_f16(acc[1][2*s+1], a1, bh[2], bh[3]);
                mma_f16(acc[0][2*s],   a0, bl[0], bl[1]);
                mma_f16(acc[0][2*s+1], a0, bl[2], bl[3]);
                mma_f16(acc[1][2*s],   a1, bl[0], bl[1]);
                mma_f16(acc[1][2*s+1], a1, bl[2], bl[3]);
            }
        }
        __syncthreads();
    }

#pragma unroll
    for (int m = 0; m < 2; ++m) {
        int r0 = bm * 128 + wm + m * 16 + (lane >> 2);
#pragma unroll
        for (int f = 0; f < 8; ++f) {
            int col = bn * 128 + wn + f * 8 + 2 * (lane & 3);
            float b0 = bias[col], b1 = bias[col + 1];
            float* p0 = g_xg + (size_t)r0 * G4 + col;
            float* p1 = p0 + (size_t)8 * G4;
            *(float2*)p0 = make_float2(acc[m][f][0] + b0, acc[m][f][1] + b1);
            *(float2*)p1 = make_float2(acc[m][f][2] + b0, acc[m][f][3] + b1);
        }
    }
}

// ---------------------------------------------------------------------------
// Grid-wide barrier (R13 central-counter version — best measured)
// ---------------------------------------------------------------------------
__device__ __forceinline__ void grid_barrier() {
    __threadfence();
    __syncthreads();
    if (threadIdx.x == 0) {
        volatile unsigned* vg = &g_gen;
        unsigned gen = *vg;
        if (atomicAdd(&g_cnt, 1u) == NBLK - 1) {
            atomicExch(&g_cnt, 0u);
            __threadfence();
            atomicAdd((unsigned*)&g_gen, 1u);
        } else {
            while (*vg == gen) { }
        }
    }
    __syncthreads();
}

// ---------------------------------------------------------------------------
// Persistent mma.sync recurrence (R13 structure, fp16 2-pass).
// Block bx: M=32 gate-cols (m=jj*4+g), N=64 batch, K=1024.
// 16 warps = 8 tiles (16m x 16n) x 2 K-sections; chunk pairs staged together.
// WhT hi/lo fp16 resident in smem; h single fp16 streamed.
// D = A_hi@h + A_lo@h, fp32 register accumulators.
// ---------------------------------------------------------------------------
__global__ void __launch_bounds__(RTH, 1)
lstm_persist(float* __restrict__ out) {
    extern __shared__ char smc[];
    const u32 sb = smem_u32(smc);
    const int tid = threadIdx.x;
    const int wid = tid >> 5;
    const int lane = tid & 31;
    const int bx = blockIdx.x;
    const int m0g = bx * 32;
    const int j0 = bx * 8;

    // one-time resident A: WhT hi/lo [32][1024] fp16
#pragma unroll
    for (int it = 0; it < 8; ++it) {
        int cid = tid + it * RTH;            // 0..4095
        int row = cid >> 7, c = cid & 127;
        size_t si = ((size_t)(m0g + row) << 10) + c * 8;
        *(uint4*)(smc + SM_AHI + row * A_STRIDE_B + c * 16) =
            __ldg((const uint4*)(g_wthi + si));
        *(uint4*)(smc + SM_ALO + row * A_STRIDE_B + c * 16) =
            __ldg((const uint4*)(g_wtlo + si));
    }

    const int tile = wid & 7;
    const int ksec = wid >> 3;               // 0 -> even chunks, 1 -> odd
    const int wm = (tile >> 2) * 16;
    const int wn = (tile & 3) * 16;

    const u32 aAddrHi = sb + SM_AHI + (u32)((wm + (lane & 15)) * A_STRIDE_B +
                                            ((lane >> 4) << 4));
    const u32 aAddrLo = aAddrHi + (u32)(SM_ALO - SM_AHI);
    const int bn_row = wn + ((lane >> 4) << 3) + (lane & 7);
    const u32 bbase = sb + SM_B + (u32)ksec * BST +
                      (u32)(bn_row * B_STRIDE_B + (((lane >> 3) & 1) << 4));

    // pointwise: one cell per thread
    const int pb = tid >> 3;                 // batch 0..63
    const int pj = tid & 7;                  // hidden col within block
    float cc = 0.0f;

    __syncthreads();

    for (int t = 0; t < T_; ++t) {
        const __half* hf = g_hf[t & 1];
        __half* hf_nxt = g_hf[(t + 1) & 1];

        float xv[4];
        {
            const float* xgb = g_xg + ((size_t)pb * T_ + t) * G4 + j0 + pj;
#pragma unroll
            for (int g = 0; g < 4; ++g) xv[g] = __ldcs(xgb + g * H_);
        }

        float acc0[4] = {0.f, 0.f, 0.f, 0.f};
        float acc1[4] = {0.f, 0.f, 0.f, 0.f};

        // stage pair 0 (chunk 0 -> buf0, chunk 1 -> buf1); chunk = K128
        // 64 rows x 16 x 16B = 1024 tasks over 512 threads x 2
#pragma unroll
        for (int q = 0; q < 2; ++q)
#pragma unroll
            for (int it = 0; it < 2; ++it) {
                int cid = tid + it * RTH;
                int row = cid >> 4, c = cid & 15;
                size_t si = ((size_t)row << 10) + q * 128 + c * 8;
                uint4 vh = __ldcg((const uint4*)(hf + si));
                *(uint4*)(smc + SM_B + q * BST + row * B_STRIDE_B + c * 16) = vh;
            }
        __syncthreads();

#pragma unroll 1
        for (int p = 0; p < 4; ++p) {
            uint4 rh[2][2];
            if (p < 3) {
#pragma unroll
                for (int q = 0; q < 2; ++q)
#pragma unroll
                    for (int it = 0; it < 2; ++it) {
                        int cid = tid + it * RTH;
                        int row = cid >> 4, c = cid & 15;
                        size_t si = ((size_t)row << 10) + (p + 1) * 256 + q * 128 + c * 8;
                        rh[q][it] = __ldcg((const uint4*)(hf + si));
                    }
            }
            // compute own chunk: kc = 2p + ksec, from buffer `ksec`
            const u32 abase = (u32)((2 * p + ksec) * 256);
#pragma unroll
            for (int kt = 0; kt < 8; ++kt) {
                u32 ahi[4], alo[4], bh[4];
                ldsm4(ahi, aAddrHi + abase + kt * 32);
                ldsm4(alo, aAddrLo + abase + kt * 32);
                ldsm4(bh, bbase + kt * 32);
                mma_f16(acc0, ahi, bh[0], bh[1]);
                mma_f16(acc1, ahi, bh[2], bh[3]);
                mma_f16(acc0, alo, bh[0], bh[1]);
                mma_f16(acc1, alo, bh[2], bh[3]);
            }
            __syncthreads();
            if (p < 3) {
#pragma unroll
                for (int q = 0; q < 2; ++q)
#pragma unroll
                    for (int it = 0; it < 2; ++it) {
                        int cid = tid + it * RTH;
                        int row = cid >> 4, c = cid & 15;
                        *(uint4*)(smc + SM_B + q * BST + row * B_STRIDE_B + c * 16) =
                            rh[q][it];
                    }
                __syncthreads();
            }
        }

        // write D fragments: Dx[ksec][32][66]
        {
            float* dx = (float*)(smc + SM_DX) + ksec * (32 * DX_S);
            int r0 = wm + (lane >> 2);
            int col = wn + 2 * (lane & 3);
            dx[r0 * DX_S + col]           = acc0[0];
            dx[r0 * DX_S + col + 1]       = acc0[1];
            dx[(r0 + 8) * DX_S + col]     = acc0[2];
            dx[(r0 + 8) * DX_S + col + 1] = acc0[3];
            dx[r0 * DX_S + col + 8]       = acc1[0];
            dx[r0 * DX_S + col + 9]       = acc1[1];
            dx[(r0 + 8) * DX_S + col + 8] = acc1[2];
            dx[(r0 + 8) * DX_S + col + 9] = acc1[3];
        }
        __syncthreads();

        // pointwise: one cell per thread
        {
            const float* dx0 = (const float*)(smc + SM_DX);
            const float* dx1 = dx0 + 32 * DX_S;
            int m = pj << 2;
            float vi = dx0[(m + 0) * DX_S + pb] + dx1[(m + 0) * DX_S + pb] + xv[0];
            float vf = dx0[(m + 1) * DX_S + pb] + dx1[(m + 1) * DX_S + pb] + xv[1];
            float vg = dx0[(m + 2) * DX_S + pb] + dx1[(m + 2) * DX_S + pb] + xv[2];
            float vo = dx0[(m + 3) * DX_S + pb] + dx1[(m + 3) * DX_S + pb] + xv[3];
            float si = 1.0f / (1.0f + expf(-vi));
            float sf = 1.0f / (1.0f + expf(-vf));
            float tg = tanhf(vg);
            float so = 1.0f / (1.0f + expf(-vo));
            float c = sf * cc + si * tg;
            cc = c;
            float h = so * tanhf(c);
            hf_nxt[(pb << 10) + j0 + pj] = __float2half_rn(h);
            out[((size_t)pb * T_ + t) * H_ + j0 + pj] = h;
        }

        if (t < T_ - 1) grid_barrier();
    }
}

// ---------------------------------------------------------------------------
// Launch: 6 graph nodes
// ---------------------------------------------------------------------------
extern "C" void kernel_launch(void* const* d_in, const int* in_sizes, int n_in,
                              void* d_out, int out_size) {
    const float* x    = (const float*)d_in[0];   // [B, T, D]
    const float* Wx   = (const float*)d_in[1];   // [D, 4H]
    const float* Wh   = (const float*)d_in[2];   // [H, 4H]
    const float* bias = (const float*)d_in[3];   // [4H]
    float* out = (float*)d_out;                  // [B, T, H]

    cudaFuncSetAttribute(lstm_persist,
                         cudaFuncAttributeMaxDynamicSharedMemorySize, SMEM_TOTAL);
    cudaFuncSetAttribute(gemm_xw_mma,
                         cudaFuncAttributeMaxDynamicSharedMemorySize, P1_SMEM);

    init_state<<<256, 256>>>();
    prep_x<<<M1 * D_ / 1024, 1024>>>(x);
    prep_wxT<<<dim3(D_ / 32, G4 / 32), dim3(32, 8)>>>(Wx);
    prep_whT<<<dim3(H_ / 32, G4 / 32), dim3(32, 8)>>>(Wh);
    gemm_xw_mma<<<dim3(G4 / 128, M1 / 128), 256, P1_SMEM>>>(bias);
    lstm_persist<<<NBLK, RTH, SMEM_TOTAL>>>(out);
}